// round 4
// baseline (speedup 1.0000x reference)
#include <cuda_runtime.h>
#include <cuda_bf16.h>
#include <math_constants.h>

// CRF neg-log-likelihood, GB300 sm_103a.
// R=4 batch rows per CTA (16 CTAs x 64 threads). Linear-space forward recursion,
// partition in bf16 smem (ping-pong per row), GEMV via 25 HFMA2 (thread j owns
// next-tag j), running log-offset, rescale by p_prev[0] every 4 steps.
// Interleaving 4 independent chains per CTA hides LDS/FMA latency behind issue;
// one BAR per superstep covers all 4 rows. Gold score epilogue; last CTA reduces.

namespace {
constexpr int NTAG   = 50;
constexpr int TSTART = NTAG - 2;   // 48
constexpr int TSTOP  = NTAG - 1;   // 49
constexpr int BATCH  = 64;
constexpr int SEQ    = 512;
constexpr int NTHR   = 64;
constexpr int R      = 4;          // rows per CTA
constexpr int NCTA   = BATCH / R;  // 16
constexpr int NPAIR  = 25;         // bf162 pairs actually summed (50 tags)
constexpr int BUFP   = 32;         // buffer pairs (64 bf16 slots, threads 50..63 pad)
}

__device__ float    g_partial[BATCH];
__device__ unsigned g_ticket = 0;

__device__ __forceinline__ float warpSumF(float v) {
#pragma unroll
    for (int o = 16; o > 0; o >>= 1) v += __shfl_xor_sync(0xffffffffu, v, o);
    return v;
}
__device__ __forceinline__ __nv_bfloat162 asbf2(float f) {
    return *reinterpret_cast<__nv_bfloat162*>(&f);
}

__global__ void __launch_bounds__(NTHR, 1)
crf_kernel(const float* __restrict__ feats,
           const int*   __restrict__ mask,
           const int*   __restrict__ tags,
           const float* __restrict__ trans,
           float*       __restrict__ out)
{
    const int g    = blockIdx.x;       // CTA -> rows g*R .. g*R+R-1
    const int j    = threadIdx.x;
    const int jf   = min(j, NTAG - 1); // clamped tag index for feat loads (pads)
    const bool act = (j < NTAG);

    __shared__ __align__(16) __nv_bfloat162 sp[R][2][BUFP];
    __shared__ int   s_mask[R * SEQ];
    __shared__ float s_fwd[R];
    __shared__ float s_acc[R];
    __shared__ int   s_len[R];
    __shared__ bool  s_last;
    __shared__ float s_red2[2];

    const float* fbr[R];
    const int*   mbr[R];
    const int*   tbr[R];
#pragma unroll
    for (int r = 0; r < R; r++) {
        int b = g * R + r;
        fbr[r] = feats + (long long)b * SEQ * NTAG;
        mbr[r] = mask  + b * SEQ;
        tbr[r] = tags  + b * SEQ;
    }

    // preload mask bits for all R rows
#pragma unroll 4
    for (int idx = j; idx < R * SEQ; idx += NTHR)
        s_mask[idx] = mbr[idx / SEQ][idx % SEQ];

    // exp(transitions) column j as bf162 pairs (shared across rows)
    __nv_bfloat162 et2[NPAIR];
    if (act) {
#pragma unroll
        for (int k = 0; k < NPAIR; k++) {
            float e0 = __expf(trans[(2 * k)     * NTAG + j]);
            float e1 = __expf(trans[(2 * k + 1) * NTAG + j]);
            et2[k] = __floats2bfloat162_rn(e0, e1);
        }
    } else {
#pragma unroll
        for (int k = 0; k < NPAIR; k++) et2[k] = __floats2bfloat162_rn(0.f, 0.f);
    }

    // per-row recursion state
    float pj[R], offs[R], ef[R], fr1[R], fr2[R], fr3[R];
#pragma unroll
    for (int r = 0; r < R; r++) {
        const float* fb = fbr[r];
        float off0 = fb[0] + trans[TSTART * NTAG + 0];
        offs[r] = off0;
        float p0 = __expf(fb[jf] + trans[TSTART * NTAG + jf] - off0);
        pj[r] = p0;
        ((__nv_bfloat16*)sp[r][0])[j] = __float2bfloat16(p0);   // pads harmless
        ef[r]  = __expf(fb[1 * NTAG + jf]);
        fr1[r] = fb[2 * NTAG + jf];
        fr2[r] = fb[3 * NTAG + jf];
        fr3[r] = fb[4 * NTAG + jf];
    }
    __syncthreads();

    // one time-step for all R rows, then one barrier
    auto superstep = [&](int t, int par, bool rescale) {
#pragma unroll
        for (int r = 0; r < R; r++) {
            // feat pipeline: prefetch t+4, exponentiate t+1
            int   tc      = min(t + 4, SEQ - 1);
            float frN     = fbr[r][tc * NTAG + jf];
            float ef_next = __expf(fr1[r]);

            const float4* s4 = (const float4*)sp[r][par];
            float4 v0 = s4[0], v1 = s4[1], v2 = s4[2];
            float4 v3 = s4[3], v4 = s4[4], v5 = s4[5];
            float  vf = ((const float*)sp[r][par])[24];         // pair 24

            float p0f = __low2float(asbf2(v0.x));

            __nv_bfloat162 z  = __floats2bfloat162_rn(0.f, 0.f);
            __nv_bfloat162 a0 = z, a1 = z, a2 = z, a3 = z;
            a0 = __hfma2(asbf2(v0.x), et2[0],  a0);
            a1 = __hfma2(asbf2(v0.y), et2[1],  a1);
            a2 = __hfma2(asbf2(v0.z), et2[2],  a2);
            a3 = __hfma2(asbf2(v0.w), et2[3],  a3);
            a0 = __hfma2(asbf2(v1.x), et2[4],  a0);
            a1 = __hfma2(asbf2(v1.y), et2[5],  a1);
            a2 = __hfma2(asbf2(v1.z), et2[6],  a2);
            a3 = __hfma2(asbf2(v1.w), et2[7],  a3);
            a0 = __hfma2(asbf2(v2.x), et2[8],  a0);
            a1 = __hfma2(asbf2(v2.y), et2[9],  a1);
            a2 = __hfma2(asbf2(v2.z), et2[10], a2);
            a3 = __hfma2(asbf2(v2.w), et2[11], a3);
            a0 = __hfma2(asbf2(v3.x), et2[12], a0);
            a1 = __hfma2(asbf2(v3.y), et2[13], a1);
            a2 = __hfma2(asbf2(v3.z), et2[14], a2);
            a3 = __hfma2(asbf2(v3.w), et2[15], a3);
            a0 = __hfma2(asbf2(v4.x), et2[16], a0);
            a1 = __hfma2(asbf2(v4.y), et2[17], a1);
            a2 = __hfma2(asbf2(v4.z), et2[18], a2);
            a3 = __hfma2(asbf2(v4.w), et2[19], a3);
            a0 = __hfma2(asbf2(v5.x), et2[20], a0);
            a1 = __hfma2(asbf2(v5.y), et2[21], a1);
            a2 = __hfma2(asbf2(v5.z), et2[22], a2);
            a3 = __hfma2(asbf2(v5.w), et2[23], a3);
            a0 = __hfma2(asbf2(vf),   et2[24], a0);

            a0 = __hadd2(a0, a1);
            a2 = __hadd2(a2, a3);
            a0 = __hadd2(a0, a2);
            float2 sf = __bfloat1622float2(a0);
            float  q  = (sf.x + sf.y) * ef[r];

            const int m = s_mask[r * SEQ + t];
            q = m ? q : pj[r];

            if (rescale) {
                q *= __frcp_rn(p0f);
                offs[r] += __logf(p0f);
            }

            pj[r] = q;
            ((__nv_bfloat16*)sp[r][par ^ 1])[j] = __float2bfloat16(q);

            ef[r] = ef_next; fr1[r] = fr2[r]; fr2[r] = fr3[r]; fr3[r] = frN;
        }
        __syncthreads();
    };

    // t = 1..508 in groups of 4 (rescale on 4th), tail 509..511
    for (int t = 1; t + 3 < SEQ; t += 4) {
        superstep(t,     0, false);
        superstep(t + 1, 1, false);
        superstep(t + 2, 0, false);
        superstep(t + 3, 1, true);
    }
    superstep(SEQ - 3, 0, false);
    superstep(SEQ - 2, 1, false);
    superstep(SEQ - 1, 0, false);
    // final partition in sp[r][1]

    // terminal: thread TSTOP owns et2 column STOP -> forward score per row
    if (j == TSTOP) {
#pragma unroll
        for (int r = 0; r < R; r++) {
            const float4* s4 = (const float4*)sp[r][1];
            __nv_bfloat162 z  = __floats2bfloat162_rn(0.f, 0.f);
            __nv_bfloat162 a0 = z, a1 = z, a2 = z, a3 = z;
#pragma unroll
            for (int k = 0; k < 6; k++) {
                float4 v = s4[k];
                a0 = __hfma2(asbf2(v.x), et2[4 * k + 0], a0);
                a1 = __hfma2(asbf2(v.y), et2[4 * k + 1], a1);
                a2 = __hfma2(asbf2(v.z), et2[4 * k + 2], a2);
                a3 = __hfma2(asbf2(v.w), et2[4 * k + 3], a3);
            }
            float vf = ((const float*)sp[r][1])[24];
            a0 = __hfma2(asbf2(vf), et2[24], a0);
            a0 = __hadd2(a0, a1);
            a2 = __hadd2(a2, a3);
            a0 = __hadd2(a0, a2);
            float2 sf = __bfloat1622float2(a0);
            s_fwd[r] = __logf(sf.x + sf.y) + offs[r];
        }
    }

    // ---- gold scores: 16 threads per row ----
    {
        const int r   = j >> 4;
        const int sub = j & 15;
        const float* fb = fbr[r];
        const int*   tb = tbr[r];
        float acc = 0.f;
        int   len = 0;
#pragma unroll 4
        for (int t = sub; t < SEQ; t += 16) {
            int tag  = tb[t];
            int prev = (t == 0) ? TSTART : tb[t - 1];
            int m    = s_mask[r * SEQ + t];
            if (m) acc += fb[t * NTAG + tag] + trans[prev * NTAG + tag];
            len += m;
        }
        // 16-lane butterfly (stays within each 16-thread group)
#pragma unroll
        for (int o = 8; o > 0; o >>= 1) {
            acc += __shfl_xor_sync(0xffffffffu, acc, o);
            len += __shfl_xor_sync(0xffffffffu, len, o);
        }
        if (sub == 0) { s_acc[r] = acc; s_len[r] = len; }
    }
    __syncthreads();

    if (j < R) {
        int   L     = s_len[j];
        int   endid = tbr[j][L - 1];
        float gold  = s_acc[j] + trans[endid * NTAG + TSTOP];
        g_partial[g * R + j] = s_fwd[j] - gold;
        __threadfence();
    }
    __syncthreads();
    if (j == 0) {
        unsigned tk = atomicAdd(&g_ticket, 1u);
        s_last = (tk == NCTA - 1);
    }
    __syncthreads();

    // last CTA out: reduce all 64 batch values, reset ticket (graph-replay safe)
    if (s_last) {
        float v = ((volatile float*)g_partial)[j];
        v = warpSumF(v);
        if ((j & 31) == 0) s_red2[j >> 5] = v;
        __syncthreads();
        if (j == 0) {
            out[0] = s_red2[0] + s_red2[1];
            g_ticket = 0;
        }
    }
}

extern "C" void kernel_launch(void* const* d_in, const int* in_sizes, int n_in,
                              void* d_out, int out_size)
{
    const float* feats = (const float*)d_in[0];
    const int*   mask  = (const int*)d_in[1];
    const int*   tags  = (const int*)d_in[2];
    const float* trans = (const float*)d_in[3];
    float* out = (float*)d_out;

    crf_kernel<<<NCTA, NTHR>>>(feats, mask, tags, trans, out);
}

// round 5
// speedup vs baseline: 2.0957x; 2.0957x over previous
#include <cuda_runtime.h>
#include <cuda_bf16.h>
#include <math_constants.h>

// CRF neg-log-likelihood, GB300 sm_103a.
// 16 CTAs x 256 threads. Each CTA processes R=4 batch rows; each row owns a
// 64-thread group (2 warps). Rows are independent chains interleaved by the
// HW warp scheduler (2 warps/SMSP); one CTA-wide barrier per step covers all
// rows' partition exchanges. Per-row step identical to the proven R3 kernel:
// linear-space recursion, bf16 partition in smem ping-pong, 25 HFMA2 GEMV,
// rescale by p_prev[0] every 4 steps, exp(feat) pipelined ahead.

namespace {
constexpr int NTAG   = 50;
constexpr int TSTART = NTAG - 2;   // 48
constexpr int TSTOP  = NTAG - 1;   // 49
constexpr int BATCH  = 64;
constexpr int SEQ    = 512;
constexpr int R      = 4;          // rows per CTA (one 64-thread group each)
constexpr int NTHR   = 64 * R;     // 256
constexpr int NCTA   = BATCH / R;  // 16
constexpr int NPAIR  = 28;         // bf162 pairs (56 slots: 50 + 6 zero pad)
}

__device__ float    g_partial[BATCH];
__device__ unsigned g_ticket = 0;

__device__ __forceinline__ float warpSumF(float v) {
#pragma unroll
    for (int o = 16; o > 0; o >>= 1) v += __shfl_xor_sync(0xffffffffu, v, o);
    return v;
}
__device__ __forceinline__ int warpSumI(int v) {
#pragma unroll
    for (int o = 16; o > 0; o >>= 1) v += __shfl_xor_sync(0xffffffffu, v, o);
    return v;
}
__device__ __forceinline__ __nv_bfloat162 asbf2(float f) {
    return *reinterpret_cast<__nv_bfloat162*>(&f);
}

// One recursion step for one row (64-thread group). Barrier NOT included.
template <bool RESCALE>
__device__ __forceinline__ void fwd_step(
    int t, int j, bool act,
    const __nv_bfloat162* __restrict__ src,
    __nv_bfloat162*       __restrict__ dst,
    const __nv_bfloat162* __restrict__ et2,
    float& ef, float& fr1, float& fr2, float& fr3,
    float& pj, float& offset,
    const float* __restrict__ fb,
    const int*   __restrict__ s_mask)
{
    // prefetch raw feat (t+4); exponentiate feat (t+1) for next step
    float frN = 0.f;
    if (act && (t + 4) < SEQ) frN = fb[(t + 4) * NTAG + j];
    float ef_next = __expf(fr1);

    const int m = s_mask[t];

    const float4* sp4 = (const float4*)src;
    float4 v0 = sp4[0];
    float4 v1 = sp4[1];
    float4 v2 = sp4[2];
    float4 v3 = sp4[3];
    float4 v4 = sp4[4];
    float4 v5 = sp4[5];
    float4 v6 = sp4[6];

    float p0f = __low2float(asbf2(v0.x));
    float rp0 = 1.f;
    if (RESCALE) rp0 = __frcp_rn(p0f);

    __nv_bfloat162 z  = __floats2bfloat162_rn(0.f, 0.f);
    __nv_bfloat162 a0 = z, a1 = z, a2 = z, a3 = z;

    a0 = __hfma2(asbf2(v0.x), et2[0],  a0);
    a1 = __hfma2(asbf2(v0.y), et2[1],  a1);
    a2 = __hfma2(asbf2(v0.z), et2[2],  a2);
    a3 = __hfma2(asbf2(v0.w), et2[3],  a3);
    a0 = __hfma2(asbf2(v1.x), et2[4],  a0);
    a1 = __hfma2(asbf2(v1.y), et2[5],  a1);
    a2 = __hfma2(asbf2(v1.z), et2[6],  a2);
    a3 = __hfma2(asbf2(v1.w), et2[7],  a3);
    a0 = __hfma2(asbf2(v2.x), et2[8],  a0);
    a1 = __hfma2(asbf2(v2.y), et2[9],  a1);
    a2 = __hfma2(asbf2(v2.z), et2[10], a2);
    a3 = __hfma2(asbf2(v2.w), et2[11], a3);
    a0 = __hfma2(asbf2(v3.x), et2[12], a0);
    a1 = __hfma2(asbf2(v3.y), et2[13], a1);
    a2 = __hfma2(asbf2(v3.z), et2[14], a2);
    a3 = __hfma2(asbf2(v3.w), et2[15], a3);
    a0 = __hfma2(asbf2(v4.x), et2[16], a0);
    a1 = __hfma2(asbf2(v4.y), et2[17], a1);
    a2 = __hfma2(asbf2(v4.z), et2[18], a2);
    a3 = __hfma2(asbf2(v4.w), et2[19], a3);
    a0 = __hfma2(asbf2(v5.x), et2[20], a0);
    a1 = __hfma2(asbf2(v5.y), et2[21], a1);
    a2 = __hfma2(asbf2(v5.z), et2[22], a2);
    a3 = __hfma2(asbf2(v5.w), et2[23], a3);
    a0 = __hfma2(asbf2(v6.x), et2[24], a0);
    a1 = __hfma2(asbf2(v6.y), et2[25], a1);
    a2 = __hfma2(asbf2(v6.z), et2[26], a2);
    a3 = __hfma2(asbf2(v6.w), et2[27], a3);

    a0 = __hadd2(a0, a1);
    a2 = __hadd2(a2, a3);
    a0 = __hadd2(a0, a2);
    float2 sf = __bfloat1622float2(a0);
    float  q  = (sf.x + sf.y) * ef;

    q = m ? q : pj;

    if (RESCALE) {
        q *= rp0;
        offset += __logf(p0f);
    }

    pj = q;
    if (act) ((__nv_bfloat16*)dst)[j] = __float2bfloat16(q);

    ef = ef_next; fr1 = fr2; fr2 = fr3; fr3 = frN;
}

__global__ void __launch_bounds__(NTHR, 1)
crf_kernel(const float* __restrict__ feats,
           const int*   __restrict__ mask,
           const int*   __restrict__ tags,
           const float* __restrict__ trans,
           float*       __restrict__ out)
{
    const int g    = blockIdx.x;        // CTA -> rows g*R .. g*R+3
    const int tid  = threadIdx.x;
    const int row  = tid >> 6;          // 0..3 (warp-pair group)
    const int j    = tid & 63;          // tag-owner index within row group
    const int lane = tid & 31;
    const int wgrp = (tid >> 5) & 1;    // which warp within the row group
    const bool act = (j < NTAG);
    const int b    = g * R + row;

    __shared__ __align__(16) __nv_bfloat162 spA[R][NPAIR];
    __shared__ __align__(16) __nv_bfloat162 spB[R][NPAIR];
    __shared__ int   s_mask[R][SEQ];
    __shared__ float s_fwd[R];
    __shared__ float s_acc[R][2];
    __shared__ int   s_len[R][2];
    __shared__ bool  s_last;
    __shared__ float s_red2[2];

    const float* fb = feats + (long long)b * SEQ * NTAG;
    const int*   mb = mask  + b * SEQ;
    const int*   tb = tags  + b * SEQ;

    // preload this row's mask bits
#pragma unroll 4
    for (int t = j; t < SEQ; t += 64) s_mask[row][t] = mb[t];

    // exp(transitions) column j as bf162 pairs (same per row; computed per thread)
    __nv_bfloat162 et2[NPAIR];
#pragma unroll
    for (int k = 0; k < NPAIR; k++) et2[k] = __floats2bfloat162_rn(0.f, 0.f);
    if (act) {
#pragma unroll
        for (int k = 0; k < 25; k++) {
            float e0 = __expf(trans[(2 * k)     * NTAG + j]);
            float e1 = __expf(trans[(2 * k + 1) * NTAG + j]);
            et2[k] = __floats2bfloat162_rn(e0, e1);
        }
    }

    // t = 0: normalize by partition0[tag 0] (per-thread computable)
    const float off0   = fb[0] + trans[TSTART * NTAG + 0];
    float       offset = off0;
    float pj = 0.f;
    if (act) pj = __expf(fb[j] + trans[TSTART * NTAG + j] - off0);
    if (j < 2 * NPAIR) {
        ((__nv_bfloat16*)spA[row])[j] = __float2bfloat16(act ? pj : 0.f);
        ((__nv_bfloat16*)spB[row])[j] = __float2bfloat16(0.f);  // zero pads once
    }

    // feat pipeline: ef = exp(feat(1)); fr1..fr3 = raw feats(2..4)
    float ef = 1.f, fr1 = 0.f, fr2 = 0.f, fr3 = 0.f;
    if (act) {
        ef  = __expf(fb[1 * NTAG + j]);
        fr1 = fb[2 * NTAG + j];
        fr2 = fb[3 * NTAG + j];
        fr3 = fb[4 * NTAG + j];
    }
    __syncthreads();

    // groups of 4 steps (rescale on 4th); one CTA barrier per step covers all rows
    for (int t = 1; t + 3 < SEQ; t += 4) {
        fwd_step<false>(t,     j, act, spA[row], spB[row], et2, ef, fr1, fr2, fr3, pj, offset, fb, s_mask[row]);
        __syncthreads();
        fwd_step<false>(t + 1, j, act, spB[row], spA[row], et2, ef, fr1, fr2, fr3, pj, offset, fb, s_mask[row]);
        __syncthreads();
        fwd_step<false>(t + 2, j, act, spA[row], spB[row], et2, ef, fr1, fr2, fr3, pj, offset, fb, s_mask[row]);
        __syncthreads();
        fwd_step<true >(t + 3, j, act, spB[row], spA[row], et2, ef, fr1, fr2, fr3, pj, offset, fb, s_mask[row]);
        __syncthreads();
    }
    // tail: t = 509, 510, 511
    fwd_step<false>(SEQ - 3, j, act, spA[row], spB[row], et2, ef, fr1, fr2, fr3, pj, offset, fb, s_mask[row]);
    __syncthreads();
    fwd_step<false>(SEQ - 2, j, act, spB[row], spA[row], et2, ef, fr1, fr2, fr3, pj, offset, fb, s_mask[row]);
    __syncthreads();
    fwd_step<false>(SEQ - 1, j, act, spA[row], spB[row], et2, ef, fr1, fr2, fr3, pj, offset, fb, s_mask[row]);
    __syncthreads();
    // final partition lives in spB[row]

    // terminal: forward = log( sum_i p[i] * exp(trans[i,STOP]) ) + offset
    if (j == TSTOP) {
        const float4* sp4 = (const float4*)spB[row];
        __nv_bfloat162 z  = __floats2bfloat162_rn(0.f, 0.f);
        __nv_bfloat162 a0 = z, a1 = z, a2 = z, a3 = z;
#pragma unroll
        for (int k = 0; k < 7; k++) {
            float4 v = sp4[k];
            a0 = __hfma2(asbf2(v.x), et2[4 * k + 0], a0);
            a1 = __hfma2(asbf2(v.y), et2[4 * k + 1], a1);
            a2 = __hfma2(asbf2(v.z), et2[4 * k + 2], a2);
            a3 = __hfma2(asbf2(v.w), et2[4 * k + 3], a3);
        }
        a0 = __hadd2(a0, a1);
        a2 = __hadd2(a2, a3);
        a0 = __hadd2(a0, a2);
        float2 sf = __bfloat1622float2(a0);
        s_fwd[row] = __logf(sf.x + sf.y) + offset;
    }

    // ---- gold score: each row's 64 threads handle their own row ----
    {
        float acc = 0.f;
        int   len = 0;
#pragma unroll 4
        for (int t = j; t < SEQ; t += 64) {
            int tag  = tb[t];
            int prev = (t == 0) ? TSTART : tb[t - 1];
            int m    = s_mask[row][t];
            if (m) acc += fb[t * NTAG + tag] + trans[prev * NTAG + tag];
            len += m;
        }
        acc = warpSumF(acc);
        len = warpSumI(len);
        if (lane == 0) { s_acc[row][wgrp] = acc; s_len[row][wgrp] = len; }
    }
    __syncthreads();

    if (tid < R) {
        const int r = tid;
        const int* tbr = tags + (long long)(g * R + r) * SEQ;
        int   L     = s_len[r][0] + s_len[r][1];
        int   endid = tbr[L - 1];
        float gold  = s_acc[r][0] + s_acc[r][1] + trans[endid * NTAG + TSTOP];
        g_partial[g * R + r] = s_fwd[r] - gold;
        __threadfence();
    }
    __syncthreads();
    if (tid == 0) {
        unsigned tk = atomicAdd(&g_ticket, 1u);
        s_last = (tk == NCTA - 1);
    }
    __syncthreads();

    // last CTA out: reduce all 64 batch values, reset ticket (graph-replay safe)
    if (s_last) {
        if (tid < BATCH) {
            float v = ((volatile float*)g_partial)[tid];
            v = warpSumF(v);
            if (lane == 0) s_red2[tid >> 5] = v;
        }
        __syncthreads();
        if (tid == 0) {
            out[0] = s_red2[0] + s_red2[1];
            g_ticket = 0;
        }
    }
}

extern "C" void kernel_launch(void* const* d_in, const int* in_sizes, int n_in,
                              void* d_out, int out_size)
{
    const float* feats = (const float*)d_in[0];
    const int*   mask  = (const int*)d_in[1];
    const int*   tags  = (const int*)d_in[2];
    const float* trans = (const float*)d_in[3];
    float* out = (float*)d_out;

    crf_kernel<<<NCTA, NTHR>>>(feats, mask, tags, trans, out);
}